// round 1
// baseline (speedup 1.0000x reference)
#include <cuda_runtime.h>
#include <math.h>

// ---------------------------------------------------------------------------
// Model1_11596411699487: 5x 4D conv (valid, stride 1) + ReLU, flatten,
// dense 1280->33 + ReLU, dense 33->2, softmax.
//
// Intermediates live in __device__ globals (no allocation allowed).
// ---------------------------------------------------------------------------

#define BATCH 256

__device__ float g_h1[BATCH * 3 * 15 * 15 * 15 * 15];  // 155.5 MB
__device__ float g_h2[BATCH * 3 * 12 * 12 * 12 * 12];  //  63.7 MB
__device__ float g_h3[BATCH * 4 * 9 * 9 * 9 * 9];      //  26.9 MB
__device__ float g_h4[BATCH * 5 * 6 * 6 * 6 * 6];      //   6.6 MB
__device__ float g_h5[BATCH * 5 * 4 * 4 * 4 * 4];      //   1.3 MB

// ---------------------------------------------------------------------------
// Direct 4D conv + ReLU.
// Each thread owns one (b, w, x, y) output position and computes ALL Sout z
// outputs for ALL Cout channels in registers. Each loaded input row of Sin
// floats feeds K*Sout*Cout FFMAs (layer1: 18 loads -> 180 FFMAs).
// Weights staged in shared memory.
// ---------------------------------------------------------------------------
template <int Cin, int Cout, int Sin, int K>
__global__ void __launch_bounds__(128)
conv4d_relu_kernel(const float* __restrict__ in,
                   const float* __restrict__ wt,
                   const float* __restrict__ bias,
                   float* __restrict__ out)
{
    constexpr int Sout = Sin - K + 1;
    constexpr int WSZ  = Cout * Cin * K * K * K * K;

    __shared__ float sw[WSZ];
    __shared__ float sb[Cout];
    for (int i = threadIdx.x; i < WSZ; i += blockDim.x) sw[i] = wt[i];
    if (threadIdx.x < Cout) sb[threadIdx.x] = bias[threadIdx.x];
    __syncthreads();

    int tid = blockIdx.x * blockDim.x + threadIdx.x;
    constexpr int NPOS = Sout * Sout * Sout;
    if (tid >= BATCH * NPOS) return;

    int y0 = tid % Sout;
    int t1 = tid / Sout;
    int x0 = t1 % Sout;
    int t2 = t1 / Sout;
    int w0 = t2 % Sout;
    int b  = t2 / Sout;

    float acc[Cout * Sout];
#pragma unroll
    for (int co = 0; co < Cout; co++)
#pragma unroll
        for (int z = 0; z < Sout; z++) acc[co * Sout + z] = sb[co];

    for (int ci = 0; ci < Cin; ci++) {
        for (int kw = 0; kw < K; kw++) {
            for (int kx = 0; kx < K; kx++) {
                for (int ky = 0; ky < K; ky++) {
                    const float* p = in +
                        ((((b * Cin + ci) * Sin + (w0 + kw)) * Sin + (x0 + kx)) * Sin
                         + (y0 + ky)) * Sin;
                    float r[Sin];
#pragma unroll
                    for (int z = 0; z < Sin; z++) r[z] = p[z];

#pragma unroll
                    for (int co = 0; co < Cout; co++) {
#pragma unroll
                        for (int kz = 0; kz < K; kz++) {
                            float wv = sw[((((co * Cin + ci) * K + kw) * K + kx) * K + ky) * K + kz];
#pragma unroll
                            for (int z = 0; z < Sout; z++)
                                acc[co * Sout + z] += r[z + kz] * wv;
                        }
                    }
                }
            }
        }
    }

#pragma unroll
    for (int co = 0; co < Cout; co++) {
        float* op = out +
            ((((b * Cout + co) * Sout + w0) * Sout + x0) * Sout + y0) * Sout;
#pragma unroll
        for (int z = 0; z < Sout; z++)
            op[z] = fmaxf(acc[co * Sout + z], 0.0f);
    }
}

// ---------------------------------------------------------------------------
// Head: per-sample block. h[b] is 1280 floats, dense 1280->33 (ReLU),
// dense 33->2, softmax.
// ---------------------------------------------------------------------------
__global__ void __launch_bounds__(64)
head_kernel(const float* __restrict__ h,
            const float* __restrict__ dw1, const float* __restrict__ db1,
            const float* __restrict__ dw2, const float* __restrict__ db2,
            float* __restrict__ out)
{
    int b = blockIdx.x;
    __shared__ float sh[1280];
    __shared__ float s1[33];

    for (int i = threadIdx.x; i < 1280; i += blockDim.x)
        sh[i] = h[b * 1280 + i];
    __syncthreads();

    int j = threadIdx.x;
    if (j < 33) {
        float s = db1[j];
        const float* wr = dw1 + j * 1280;
#pragma unroll 4
        for (int i = 0; i < 1280; i++) s += wr[i] * sh[i];
        s1[j] = fmaxf(s, 0.0f);
    }
    __syncthreads();

    if (threadIdx.x == 0) {
        float l0 = db2[0], l1 = db2[1];
        for (int jj = 0; jj < 33; jj++) {
            l0 += dw2[jj] * s1[jj];
            l1 += dw2[33 + jj] * s1[jj];
        }
        float m  = fmaxf(l0, l1);
        float e0 = expf(l0 - m);
        float e1 = expf(l1 - m);
        float inv = 1.0f / (e0 + e1);
        out[b * 2 + 0] = e0 * inv;
        out[b * 2 + 1] = e1 * inv;
    }
}

static inline int cdiv(int a, int b) { return (a + b - 1) / b; }

extern "C" void kernel_launch(void* const* d_in, const int* in_sizes, int n_in,
                              void* d_out, int out_size)
{
    const float* x   = (const float*)d_in[0];
    const float* w1  = (const float*)d_in[1];
    const float* b1  = (const float*)d_in[2];
    const float* w2  = (const float*)d_in[3];
    const float* b2  = (const float*)d_in[4];
    const float* w3  = (const float*)d_in[5];
    const float* b3  = (const float*)d_in[6];
    const float* w4  = (const float*)d_in[7];
    const float* b4  = (const float*)d_in[8];
    const float* w5  = (const float*)d_in[9];
    const float* b5  = (const float*)d_in[10];
    const float* dw1 = (const float*)d_in[11];
    const float* db1 = (const float*)d_in[12];
    const float* dw2 = (const float*)d_in[13];
    const float* db2 = (const float*)d_in[14];
    float* out = (float*)d_out;

    float *h1, *h2, *h3, *h4, *h5;
    cudaGetSymbolAddress((void**)&h1, g_h1);
    cudaGetSymbolAddress((void**)&h2, g_h2);
    cudaGetSymbolAddress((void**)&h3, g_h3);
    cudaGetSymbolAddress((void**)&h4, g_h4);
    cudaGetSymbolAddress((void**)&h5, g_h5);

    const int T = 128;

    // conv1: 1->3, 18->15, k=4
    conv4d_relu_kernel<1, 3, 18, 4><<<cdiv(BATCH * 15 * 15 * 15, T), T>>>(x, w1, b1, h1);
    // conv2: 3->3, 15->12, k=4
    conv4d_relu_kernel<3, 3, 15, 4><<<cdiv(BATCH * 12 * 12 * 12, T), T>>>(h1, w2, b2, h2);
    // conv3: 3->4, 12->9, k=4
    conv4d_relu_kernel<3, 4, 12, 4><<<cdiv(BATCH * 9 * 9 * 9, T), T>>>(h2, w3, b3, h3);
    // conv4: 4->5, 9->6, k=4
    conv4d_relu_kernel<4, 5, 9, 4><<<cdiv(BATCH * 6 * 6 * 6, T), T>>>(h3, w4, b4, h4);
    // conv5: 5->5, 6->4, k=3
    conv4d_relu_kernel<5, 5, 6, 3><<<cdiv(BATCH * 4 * 4 * 4, T), T>>>(h4, w5, b5, h5);
    // head
    head_kernel<<<BATCH, 64>>>(h5, dw1, db1, dw2, db2, out);
}